// round 10
// baseline (speedup 1.0000x reference)
#include <cuda_runtime.h>
#include <cuda_fp16.h>

#define B_  16
#define S_  2048
#define D_  128
#define TM  128         // q rows per CTA
#define TN  64          // k rows per tile
#define KTILES (S_/TN)  // 32
#define THREADS 256
#define CTX_ELEMS (B_*S_*D_)

// fp16 copies of K and V, produced once by convert_kv (8.4 MB each)
__device__ __half g_Kh[B_*S_*D_];
__device__ __half g_Vh[B_*S_*D_];

// dynamic smem layout (halfs, 136-stride rows: 272B, conflict-free, 16B-aligned)
#define QS_BYTES (TM*136*2)              // 34816
#define KS_BYTES (2*TN*136*2)            // 34816 (double-buffered)
#define SMEM_MAIN (QS_BYTES + 2*KS_BYTES)

__device__ __forceinline__ unsigned smem_u32(const void* p) {
    return (unsigned)__cvta_generic_to_shared(p);
}
__device__ __forceinline__ unsigned packh2(float a, float b) {
    __half2 h = __floats2half2_rn(a, b);
    return *reinterpret_cast<unsigned*>(&h);
}
__device__ __forceinline__ float ex2f(float x) {
    float y;
    asm volatile("ex2.approx.ftz.f32 %0, %1;" : "=f"(y) : "f"(x));
    return y;
}
__device__ __forceinline__ void mma16816(float c[4], const unsigned a[4],
                                         unsigned b0, unsigned b1) {
    asm volatile(
        "mma.sync.aligned.m16n8k16.row.col.f32.f16.f16.f32 "
        "{%0,%1,%2,%3}, {%4,%5,%6,%7}, {%8,%9}, {%0,%1,%2,%3};"
        : "+f"(c[0]), "+f"(c[1]), "+f"(c[2]), "+f"(c[3])
        : "r"(a[0]), "r"(a[1]), "r"(a[2]), "r"(a[3]), "r"(b0), "r"(b1));
}
__device__ __forceinline__ void ldmx4(unsigned& r0, unsigned& r1,
                                      unsigned& r2, unsigned& r3, unsigned a) {
    asm volatile("ldmatrix.sync.aligned.m8n8.x4.shared.b16 {%0,%1,%2,%3}, [%4];"
                 : "=r"(r0), "=r"(r1), "=r"(r2), "=r"(r3) : "r"(a));
}
__device__ __forceinline__ void ldmx4t(unsigned& r0, unsigned& r1,
                                       unsigned& r2, unsigned& r3, unsigned a) {
    asm volatile("ldmatrix.sync.aligned.m8n8.x4.trans.shared.b16 {%0,%1,%2,%3}, [%4];"
                 : "=r"(r0), "=r"(r1), "=r"(r2), "=r"(r3) : "r"(a));
}
__device__ __forceinline__ void cp16(void* sdst, const void* gsrc) {
    asm volatile("cp.async.cg.shared.global [%0], [%1], 16;"
                 :: "r"(smem_u32(sdst)), "l"(gsrc));
}

// Prep: fp32 K/V -> fp16 device globals (one-shot, ~8us, DRAM-bound).
__global__ void __launch_bounds__(256) convert_kv(
    const float4* __restrict__ k4, const float4* __restrict__ v4)
{
    const size_t i = (size_t)blockIdx.x * 256 + threadIdx.x;
    float4 a = k4[i];
    float4 b = v4[i];
    uint2 ua, ub;
    ua.x = packh2(a.x, a.y); ua.y = packh2(a.z, a.w);
    ub.x = packh2(b.x, b.y); ub.y = packh2(b.z, b.w);
    ((uint2*)g_Kh)[i] = ua;
    ((uint2*)g_Vh)[i] = ub;
}

// Fused attention: per (batch, 128-row q-tile), 8 warps, 2 CTAs/SM.
//  Phase 1: S=(Q*scale*log2e)@K^T (fp16 mma; Q from smem, K/V fp16 tiles via
//    double-buffered cp.async), p=ex2(S) -> unnormalized half2 probs to gmem,
//    rowsum Z in regs, ctx += P@V.
//  Phase 2: in-place expand of this CTA's 128 attn rows (fp16 -> norm fp32).
__global__ void __launch_bounds__(THREADS, 2) attn_fused(
    const float* __restrict__ q, float* __restrict__ out)
{
    extern __shared__ __align__(16) char smraw[];
    half* Qs = (half*)smraw;                          // [128][136]
    half* Ks = (half*)(smraw + QS_BYTES);             // [2][64][136]
    half* Vs = (half*)(smraw + QS_BYTES + KS_BYTES);  // [2][64][136]
    __shared__ float zbuf[TM];

#define QS_(r,c)    Qs[(r)*136 + (c)]
#define KS_(bb,r,c) Ks[((bb)*TN + (r))*136 + (c)]
#define VS_(bb,r,c) Vs[((bb)*TN + (r))*136 + (c)]

    float* ctx   = out;
    float* attn  = out + CTX_ELEMS;
    half*  attnh = (half*)(out + CTX_ELEMS);   // packed fp16 probs (low half of rows)

    const int b    = blockIdx.y;
    const int qt   = blockIdx.x;
    const int tid  = threadIdx.x;
    const int w    = tid >> 5;
    const int lane = tid & 31;
    const int g    = lane >> 2;
    const int i4   = lane & 3;

    const int gr0 = b * S_ + qt * TM;
    const int lr0 = w * 16 + g;
    const int lr1 = lr0 + 8;
    const int r0 = gr0 + lr0;
    const int r1 = gr0 + lr1;

    const half* gK = g_Kh + (size_t)b * S_ * D_;
    const half* gV = g_Vh + (size_t)b * S_ * D_;

    // ---- Q -> smem fp16 with scale*log2e folded ----
    {
        const float SC = 0.08838834764831845f * 1.4426950408889634f;
        const int qr = tid >> 1, cb = (tid & 1) * 64;
        const float* qg = q + (size_t)(gr0 + qr) * D_ + cb;
        #pragma unroll
        for (int j = 0; j < 16; j++) {
            float4 x = *(const float4*)(qg + j * 4);
            uint2 u;
            u.x = packh2(x.x * SC, x.y * SC);
            u.y = packh2(x.z * SC, x.w * SC);
            *(uint2*)&QS_(qr, cb + j * 4) = u;
        }
    }

    // cp.async K/V tile kt into buffer bb (16KB each, 4 chunks/thread/tensor)
    auto issue_tile = [&](int kt, int bb) {
        const half* kg = gK + (size_t)kt * TN * D_;
        const half* vg = gV + (size_t)kt * TN * D_;
        #pragma unroll
        for (int c = 0; c < 4; c++) {
            const int idx = c * THREADS + tid;
            const int row = idx >> 4;
            const int ch  = (idx & 15) * 8;
            cp16(&KS_(bb, row, ch), kg + row * D_ + ch);
            cp16(&VS_(bb, row, ch), vg + row * D_ + ch);
        }
        asm volatile("cp.async.commit_group;");
    };
    issue_tile(0, 0);

    float acc[16][4];
    #pragma unroll
    for (int nt = 0; nt < 16; nt++)
        #pragma unroll
        for (int j = 0; j < 4; j++) acc[nt][j] = 0.f;
    float zp0 = 0.f, zp1 = 0.f;

    const int lm_row = (lane & 7);
    const int lm_m   = lane >> 3;
    const unsigned qaddr0 = smem_u32(&QS_(w * 16 + (lane & 15), (lane >> 4) * 8));

    for (int kt = 0; kt < KTILES; kt++) {
        const int bb = kt & 1;
        asm volatile("cp.async.wait_group 0;" ::: "memory");
        __syncthreads();   // tile bb ready; buffer bb^1 fully consumed

        if (kt + 1 < KTILES) issue_tile(kt + 1, bb ^ 1);

        // ---- QK: S tile m16 x n64 per warp ----
        float sc[8][4];
        #pragma unroll
        for (int nt = 0; nt < 8; nt++)
            #pragma unroll
            for (int j = 0; j < 4; j++) sc[nt][j] = 0.f;

        #pragma unroll
        for (int ks = 0; ks < 8; ks++) {
            unsigned aqf[4];
            ldmx4(aqf[0], aqf[1], aqf[2], aqf[3], qaddr0 + ks * 32);
            unsigned kb[8][2];
            #pragma unroll
            for (int p = 0; p < 4; p++) {
                const int row = p * 16 + (lm_m >> 1) * 8 + lm_row;
                const int col = ks * 16 + (lm_m & 1) * 8;
                ldmx4(kb[2*p][0], kb[2*p][1], kb[2*p+1][0], kb[2*p+1][1],
                      smem_u32(&KS_(bb, row, col)));
            }
            #pragma unroll
            for (int nt = 0; nt < 8; nt++)
                mma16816(sc[nt], aqf, kb[nt][0], kb[nt][1]);
        }

        // ---- exp + rowsum + pack half2 ----
        unsigned ph0[8], ph1[8];
        #pragma unroll
        for (int nt = 0; nt < 8; nt++) {
            float e0 = ex2f(sc[nt][0]), e1 = ex2f(sc[nt][1]);
            float e2 = ex2f(sc[nt][2]), e3 = ex2f(sc[nt][3]);
            zp0 += e0 + e1;
            zp1 += e2 + e3;
            ph0[nt] = packh2(e0, e1);
            ph1[nt] = packh2(e2, e3);
        }

        // ---- PV: ctx += P @ V (half2 probs reused as A-frags) ----
        #pragma unroll
        for (int kk = 0; kk < 4; kk++) {
            unsigned pa[4] = { ph0[2*kk], ph1[2*kk], ph0[2*kk+1], ph1[2*kk+1] };
            #pragma unroll
            for (int ntp = 0; ntp < 8; ntp++) {
                const int row = kk * 16 + (lm_m & 1) * 8 + lm_row;
                const int col = (ntp * 2 + (lane >> 4)) * 8;
                unsigned b0, b1, b2, b3;
                ldmx4t(b0, b1, b2, b3, smem_u32(&VS_(bb, row, col)));
                mma16816(acc[2*ntp],     pa, b0, b1);
                mma16816(acc[2*ntp + 1], pa, b2, b3);
            }
        }

        // ---- store packed probs (off the critical path) ----
        {
            half* a0 = attnh + (size_t)r0 * 4096 + kt * TN + 2 * i4;
            half* a1 = attnh + (size_t)r1 * 4096 + kt * TN + 2 * i4;
            #pragma unroll
            for (int nt = 0; nt < 8; nt++) {
                *(unsigned*)(a0 + nt * 8) = ph0[nt];
                *(unsigned*)(a1 + nt * 8) = ph1[nt];
            }
        }
    }

    // ---- rowsum reduce (4 lanes share a row) ----
    float z0 = zp0;
    z0 += __shfl_xor_sync(0xffffffffu, z0, 1);
    z0 += __shfl_xor_sync(0xffffffffu, z0, 2);
    float z1 = zp1;
    z1 += __shfl_xor_sync(0xffffffffu, z1, 1);
    z1 += __shfl_xor_sync(0xffffffffu, z1, 2);
    const float iz0 = 1.0f / z0;
    const float iz1 = 1.0f / z1;
    if (i4 == 0) {
        zbuf[lr0] = iz0;
        zbuf[lr1] = iz1;
    }

    // ---- normalized context writeback ----
    float* c0p = ctx + (size_t)r0 * D_ + 2 * i4;
    float* c1p = ctx + (size_t)r1 * D_ + 2 * i4;
    #pragma unroll
    for (int nt = 0; nt < 16; nt++) {
        *(float2*)(c0p + nt * 8) = make_float2(acc[nt][0] * iz0, acc[nt][1] * iz0);
        *(float2*)(c1p + nt * 8) = make_float2(acc[nt][2] * iz1, acc[nt][3] * iz1);
    }

    // ================= tail: in-place expand this CTA's attn rows ===========
    __syncthreads();

    const int t = tid & 63;                 // 64 threads per row
    #pragma unroll 1
    for (int c = 0; c < TM / 4; c++) {      // 4 rows per pass
        const int lr = c * 4 + (tid >> 6);
        const float iz = zbuf[lr];
        const uint4* src = (const uint4*)(attnh + (size_t)(gr0 + lr) * 4096);

        float4 outv[8];
        #pragma unroll
        for (int j = 0; j < 4; j++) {
            uint4 raw = src[t + j * 64];
            const __half2* hp = (const __half2*)&raw;
            float2 f0 = __half22float2(hp[0]);
            float2 f1 = __half22float2(hp[1]);
            float2 f2 = __half22float2(hp[2]);
            float2 f3 = __half22float2(hp[3]);
            outv[2*j]   = make_float4(f0.x * iz, f0.y * iz, f1.x * iz, f1.y * iz);
            outv[2*j+1] = make_float4(f2.x * iz, f2.y * iz, f3.x * iz, f3.y * iz);
        }
        __syncthreads();   // all reads of these 4 rows complete before writes

        float4* dst = (float4*)(attn + (size_t)(gr0 + lr) * S_);
        #pragma unroll
        for (int j = 0; j < 4; j++) {
            dst[2 * (t + j * 64)]     = outv[2*j];
            dst[2 * (t + j * 64) + 1] = outv[2*j+1];
        }
    }
}

extern "C" void kernel_launch(void* const* d_in, const int* in_sizes, int n_in,
                              void* d_out, int out_size)
{
    const float* q = (const float*)d_in[0];
    const float* k = (const float*)d_in[1];
    const float* v = (const float*)d_in[2];
    float* out = (float*)d_out;

    static bool attr_set = false;
    if (!attr_set) {
        cudaFuncSetAttribute(attn_fused, cudaFuncAttributeMaxDynamicSharedMemorySize,
                             SMEM_MAIN);
        attr_set = true;
    }

    convert_kv<<<(B_ * S_ * D_) / 4 / 256, 256>>>((const float4*)k, (const float4*)v);
    dim3 g1(S_ / TM, B_);
    attn_fused<<<g1, THREADS, SMEM_MAIN>>>(q, out);
}

// round 12
// speedup vs baseline: 1.4347x; 1.4347x over previous
#include <cuda_runtime.h>
#include <cuda_fp16.h>

#define B_  16
#define S_  2048
#define D_  128
#define TM  128         // q rows per CTA (8 pairs x 16 rows)
#define TN  64          // k rows per tile
#define KTILES (S_/TN)  // 32
#define THREADS 512
#define CTX_ELEMS (B_*S_*D_)

// fp16 copies of K and V, produced once by convert_kv
__device__ __half g_Kh[B_*S_*D_];
__device__ __half g_Vh[B_*S_*D_];

// dynamic smem: K/V double-buffered fp16 tiles + P-exchange buffer
#define KS_BYTES (2*TN*136*2)            // 34816 per tensor (double-buffered)
#define PS_STRIDE 72                     // halfs per P row (144B, conflict-free)
#define PS_BYTES (8*16*PS_STRIDE*2)      // 18432
#define SMEM_MAIN (2*KS_BYTES + PS_BYTES)

__device__ __forceinline__ unsigned smem_u32(const void* p) {
    return (unsigned)__cvta_generic_to_shared(p);
}
__device__ __forceinline__ unsigned packh2(float a, float b) {
    __half2 h = __floats2half2_rn(a, b);
    return *reinterpret_cast<unsigned*>(&h);
}
__device__ __forceinline__ float ex2f(float x) {
    float y;
    asm volatile("ex2.approx.ftz.f32 %0, %1;" : "=f"(y) : "f"(x));
    return y;
}
__device__ __forceinline__ void mma16816(float c[4], const unsigned a[4],
                                         unsigned b0, unsigned b1) {
    asm volatile(
        "mma.sync.aligned.m16n8k16.row.col.f32.f16.f16.f32 "
        "{%0,%1,%2,%3}, {%4,%5,%6,%7}, {%8,%9}, {%0,%1,%2,%3};"
        : "+f"(c[0]), "+f"(c[1]), "+f"(c[2]), "+f"(c[3])
        : "r"(a[0]), "r"(a[1]), "r"(a[2]), "r"(a[3]), "r"(b0), "r"(b1));
}
__device__ __forceinline__ void ldmx4(unsigned& r0, unsigned& r1,
                                      unsigned& r2, unsigned& r3, unsigned a) {
    asm volatile("ldmatrix.sync.aligned.m8n8.x4.shared.b16 {%0,%1,%2,%3}, [%4];"
                 : "=r"(r0), "=r"(r1), "=r"(r2), "=r"(r3) : "r"(a));
}
__device__ __forceinline__ void ldmx4t(unsigned& r0, unsigned& r1,
                                       unsigned& r2, unsigned& r3, unsigned a) {
    asm volatile("ldmatrix.sync.aligned.m8n8.x4.trans.shared.b16 {%0,%1,%2,%3}, [%4];"
                 : "=r"(r0), "=r"(r1), "=r"(r2), "=r"(r3) : "r"(a));
}
__device__ __forceinline__ void cp16(void* sdst, const void* gsrc) {
    asm volatile("cp.async.cg.shared.global [%0], [%1], 16;"
                 :: "r"(smem_u32(sdst)), "l"(gsrc));
}

// Prep: fp32 K/V -> fp16 device globals (one-shot, DRAM-bound, ~8us).
__global__ void __launch_bounds__(256) convert_kv(
    const float4* __restrict__ k4, const float4* __restrict__ v4)
{
    const size_t i = (size_t)blockIdx.x * 256 + threadIdx.x;
    float4 a = k4[i];
    float4 b = v4[i];
    uint2 ua, ub;
    ua.x = packh2(a.x, a.y); ua.y = packh2(a.z, a.w);
    ub.x = packh2(b.x, b.y); ub.y = packh2(b.z, b.w);
    ((uint2*)g_Kh)[i] = ua;
    ((uint2*)g_Vh)[i] = ub;
}

// Fused attention: 512 threads = 8 warp-pairs; pair owns 16 q-rows.
// Within a pair, half h does QK for keys [h*32,h*32+32) and PV for
// d-cols [h*64,h*64+64); P halves exchanged via smem (A-frag reload).
__global__ void __launch_bounds__(THREADS, 1) attn_fused(
    const float* __restrict__ q, float* __restrict__ out)
{
    extern __shared__ __align__(16) char smraw[];
    half* Ks = (half*)smraw;                     // [2][64][136]
    half* Vs = (half*)(smraw + KS_BYTES);        // [2][64][136]
    half* Ps = (half*)(smraw + 2 * KS_BYTES);    // [8 pairs][16][72]
    __shared__ float zsh[2][TM];
    __shared__ float izbuf[TM];

#define KS_(bb,r,c) Ks[((bb)*TN + (r))*136 + (c)]
#define VS_(bb,r,c) Vs[((bb)*TN + (r))*136 + (c)]
#define PS_(pp,r,c) Ps[((pp)*16 + (r))*PS_STRIDE + (c)]

    float* ctx   = out;
    float* attn  = out + CTX_ELEMS;
    half*  attnh = (half*)(out + CTX_ELEMS);   // packed fp16 probs (low half of rows)

    const int b    = blockIdx.y;
    const int qt   = blockIdx.x;
    const int tid  = threadIdx.x;
    const int w    = tid >> 5;
    const int lane = tid & 31;
    const int g    = lane >> 2;
    const int i4   = lane & 3;
    const int pr   = w >> 1;     // pair index 0..7
    const int h    = w & 1;      // half within pair

    const int gr0 = b * S_ + qt * TM;
    const int lr0 = pr * 16 + g;
    const int lr1 = lr0 + 8;
    const int r0 = gr0 + lr0;
    const int r1 = gr0 + lr1;

    const half* gK = g_Kh + (size_t)b * S_ * D_;
    const half* gV = g_Vh + (size_t)b * S_ * D_;

    // ---- Q fragments in regs, scale*log2e folded ----
    const float SC = 0.08838834764831845f * 1.4426950408889634f;
    unsigned aq[8][4];
    {
        const float* q0 = q + (size_t)r0 * D_;
        const float* q1 = q + (size_t)r1 * D_;
        #pragma unroll
        for (int ks = 0; ks < 8; ks++) {
            const int c = ks * 16 + 2 * i4;
            float2 x0 = *(const float2*)(q0 + c);
            float2 x1 = *(const float2*)(q1 + c);
            float2 x2 = *(const float2*)(q0 + c + 8);
            float2 x3 = *(const float2*)(q1 + c + 8);
            aq[ks][0] = packh2(x0.x * SC, x0.y * SC);
            aq[ks][1] = packh2(x1.x * SC, x1.y * SC);
            aq[ks][2] = packh2(x2.x * SC, x2.y * SC);
            aq[ks][3] = packh2(x3.x * SC, x3.y * SC);
        }
    }

    // cp.async K/V tile kt into buffer bb (16KB each; 2 chunks/thread/tensor)
    auto issue_tile = [&](int kt, int bb) {
        const half* kg = gK + (size_t)kt * TN * D_;
        const half* vg = gV + (size_t)kt * TN * D_;
        #pragma unroll
        for (int c = 0; c < 2; c++) {
            const int idx = c * THREADS + tid;
            const int row = idx >> 4;
            const int ch  = (idx & 15) * 8;
            cp16(&KS_(bb, row, ch), kg + row * D_ + ch);
            cp16(&VS_(bb, row, ch), vg + row * D_ + ch);
        }
        asm volatile("cp.async.commit_group;");
    };
    issue_tile(0, 0);

    float acc[8][4];     // ctx m16 x d64 (this half's columns)
    #pragma unroll
    for (int nt = 0; nt < 8; nt++)
        #pragma unroll
        for (int j = 0; j < 4; j++) acc[nt][j] = 0.f;
    float zp0 = 0.f, zp1 = 0.f;

    const int lm_row = (lane & 7);
    const int lm_m   = lane >> 3;
    // P A-frag base address (this pair's exchange buffer)
    const unsigned paddr0 = smem_u32(&PS_(pr, (lane & 15), (lane >> 4) * 8));

    for (int kt = 0; kt < KTILES; kt++) {
        const int bb = kt & 1;
        asm volatile("cp.async.wait_group 0;" ::: "memory");
        __syncthreads();   // K/V tile bb ready; Ps from prev tile consumed

        if (kt + 1 < KTILES) issue_tile(kt + 1, bb ^ 1);

        // ---- QK: m16 x n32 per warp (keys h*32 .. h*32+31) ----
        float sc[4][4];
        #pragma unroll
        for (int nt = 0; nt < 4; nt++)
            #pragma unroll
            for (int j = 0; j < 4; j++) sc[nt][j] = 0.f;

        #pragma unroll
        for (int ks = 0; ks < 8; ks++) {
            unsigned kb[4][2];
            #pragma unroll
            for (int p2 = 0; p2 < 2; p2++) {
                const int row = h * 32 + p2 * 16 + (lm_m >> 1) * 8 + lm_row;
                const int col = ks * 16 + (lm_m & 1) * 8;
                ldmx4(kb[2*p2][0], kb[2*p2][1], kb[2*p2+1][0], kb[2*p2+1][1],
                      smem_u32(&KS_(bb, row, col)));
            }
            #pragma unroll
            for (int nt = 0; nt < 4; nt++)
                mma16816(sc[nt], aq[ks], kb[nt][0], kb[nt][1]);
        }

        // ---- exp + rowsum + pack half2 ----
        unsigned ph0[4], ph1[4];
        #pragma unroll
        for (int nt = 0; nt < 4; nt++) {
            float e0 = ex2f(sc[nt][0]), e1 = ex2f(sc[nt][1]);
            float e2 = ex2f(sc[nt][2]), e3 = ex2f(sc[nt][3]);
            zp0 += e0 + e1;
            zp1 += e2 + e3;
            ph0[nt] = packh2(e0, e1);
            ph1[nt] = packh2(e2, e3);
        }

        // ---- store packed probs (this half's 32 key-columns) ----
        {
            half* a0 = attnh + (size_t)r0 * 4096 + kt * TN + h * 32 + 2 * i4;
            half* a1 = attnh + (size_t)r1 * 4096 + kt * TN + h * 32 + 2 * i4;
            #pragma unroll
            for (int nt = 0; nt < 4; nt++) {
                *(unsigned*)(a0 + nt * 8) = ph0[nt];
                *(unsigned*)(a1 + nt * 8) = ph1[nt];
            }
        }

        // ---- publish P half to pair exchange buffer ----
        #pragma unroll
        for (int nt = 0; nt < 4; nt++) {
            const int col = h * 32 + nt * 8 + 2 * i4;
            *(unsigned*)&PS_(pr, g,     col) = ph0[nt];
            *(unsigned*)&PS_(pr, g + 8, col) = ph1[nt];
        }
        __syncthreads();   // full P (both halves) visible

        // ---- PV: ctx(d-half h) += P @ V ----
        #pragma unroll
        for (int kk = 0; kk < 4; kk++) {
            unsigned pa[4];
            ldmx4(pa[0], pa[1], pa[2], pa[3], paddr0 + kk * 32);
            #pragma unroll
            for (int ntp = 0; ntp < 4; ntp++) {
                const int row = kk * 16 + (lane & 15);
                const int col = h * 64 + (ntp * 2 + (lane >> 4)) * 8;
                unsigned b0, b1, b2, b3;
                ldmx4t(b0, b1, b2, b3, smem_u32(&VS_(bb, row, col)));
                mma16816(acc[2*ntp],     pa, b0, b1);
                mma16816(acc[2*ntp + 1], pa, b2, b3);
            }
        }
    }

    // ---- rowsum: reduce i4 lanes, combine pair halves via smem ----
    float z0 = zp0;
    z0 += __shfl_xor_sync(0xffffffffu, z0, 1);
    z0 += __shfl_xor_sync(0xffffffffu, z0, 2);
    float z1 = zp1;
    z1 += __shfl_xor_sync(0xffffffffu, z1, 1);
    z1 += __shfl_xor_sync(0xffffffffu, z1, 2);
    if (i4 == 0) {
        zsh[h][lr0] = z0;
        zsh[h][lr1] = z1;
    }
    __syncthreads();
    const float iz0 = 1.0f / (zsh[0][lr0] + zsh[1][lr0]);
    const float iz1 = 1.0f / (zsh[0][lr1] + zsh[1][lr1]);
    if (h == 0 && i4 == 0) {
        izbuf[lr0] = iz0;
        izbuf[lr1] = iz1;
    }

    // ---- normalized context writeback (this half's 64 d-columns) ----
    float* c0p = ctx + (size_t)r0 * D_ + h * 64 + 2 * i4;
    float* c1p = ctx + (size_t)r1 * D_ + h * 64 + 2 * i4;
    #pragma unroll
    for (int nt = 0; nt < 8; nt++) {
        *(float2*)(c0p + nt * 8) = make_float2(acc[nt][0] * iz0, acc[nt][1] * iz0);
        *(float2*)(c1p + nt * 8) = make_float2(acc[nt][2] * iz1, acc[nt][3] * iz1);
    }

    // ================= tail: in-place expand this CTA's attn rows ===========
    __syncthreads();   // probs + izbuf visible CTA-wide

    const int t = tid & 127;                // 128 threads per row
    #pragma unroll 1
    for (int c = 0; c < TM / 4; c++) {      // 4 rows per pass
        const int lr = c * 4 + (tid >> 7);
        const float iz = izbuf[lr];
        const uint4* src = (const uint4*)(attnh + (size_t)(gr0 + lr) * 4096);

        float4 outv[4];
        #pragma unroll
        for (int j = 0; j < 2; j++) {
            uint4 raw = src[t + j * 128];
            const __half2* hp = (const __half2*)&raw;
            float2 f0 = __half22float2(hp[0]);
            float2 f1 = __half22float2(hp[1]);
            float2 f2 = __half22float2(hp[2]);
            float2 f3 = __half22float2(hp[3]);
            outv[2*j]   = make_float4(f0.x * iz, f0.y * iz, f1.x * iz, f1.y * iz);
            outv[2*j+1] = make_float4(f2.x * iz, f2.y * iz, f3.x * iz, f3.y * iz);
        }
        __syncthreads();   // all reads of these 4 rows complete before writes

        float4* dst = (float4*)(attn + (size_t)(gr0 + lr) * S_);
        #pragma unroll
        for (int j = 0; j < 2; j++) {
            dst[2 * (t + j * 128)]     = outv[2*j];
            dst[2 * (t + j * 128) + 1] = outv[2*j+1];
        }
    }
}

extern "C" void kernel_launch(void* const* d_in, const int* in_sizes, int n_in,
                              void* d_out, int out_size)
{
    const float* q = (const float*)d_in[0];
    const float* k = (const float*)d_in[1];
    const float* v = (const float*)d_in[2];
    float* out = (float*)d_out;

    static bool attr_set = false;
    if (!attr_set) {
        cudaFuncSetAttribute(attn_fused, cudaFuncAttributeMaxDynamicSharedMemorySize,
                             SMEM_MAIN);
        attr_set = true;
    }

    convert_kv<<<(B_ * S_ * D_) / 4 / 256, 256>>>((const float4*)k, (const float4*)v);
    dim3 g1(S_ / TM, B_);
    attn_fused<<<g1, THREADS, SMEM_MAIN>>>(q, out);
}

// round 14
// speedup vs baseline: 1.5127x; 1.0544x over previous
#include <cuda_runtime.h>
#include <cuda_fp16.h>

#define B_  16
#define S_  2048
#define D_  128
#define TM  128         // q rows per CTA (8 warps x 16 rows per role)
#define TN  64          // k rows per tile
#define KTILES (S_/TN)  // 32
#define THREADS 512
#define CTX_ELEMS (B_*S_*D_)

// fp16 copies of K and V, produced once by convert_kv
__device__ __half g_Kh[B_*S_*D_];
__device__ __half g_Vh[B_*S_*D_];

// dynamic smem: K/V double-buffered fp16 tiles + double-buffered P ring
#define KS_BYTES (2*TN*136*2)            // 34816 per tensor (double-buffered)
#define PS_STRIDE 72                     // halfs per P row (144B, conflict-free)
#define PS_BYTES (2*8*16*PS_STRIDE*2)    // 36864 (double-buffered ring)
#define SMEM_MAIN (2*KS_BYTES + PS_BYTES)

__device__ __forceinline__ unsigned smem_u32(const void* p) {
    return (unsigned)__cvta_generic_to_shared(p);
}
__device__ __forceinline__ unsigned packh2(float a, float b) {
    __half2 h = __floats2half2_rn(a, b);
    return *reinterpret_cast<unsigned*>(&h);
}
__device__ __forceinline__ float ex2f(float x) {
    float y;
    asm volatile("ex2.approx.ftz.f32 %0, %1;" : "=f"(y) : "f"(x));
    return y;
}
__device__ __forceinline__ void barsync() {
    asm volatile("bar.sync 0;" ::: "memory");
}
__device__ __forceinline__ void mma16816(float c[4], const unsigned a[4],
                                         unsigned b0, unsigned b1) {
    asm volatile(
        "mma.sync.aligned.m16n8k16.row.col.f32.f16.f16.f32 "
        "{%0,%1,%2,%3}, {%4,%5,%6,%7}, {%8,%9}, {%0,%1,%2,%3};"
        : "+f"(c[0]), "+f"(c[1]), "+f"(c[2]), "+f"(c[3])
        : "r"(a[0]), "r"(a[1]), "r"(a[2]), "r"(a[3]), "r"(b0), "r"(b1));
}
__device__ __forceinline__ void ldmx4(unsigned& r0, unsigned& r1,
                                      unsigned& r2, unsigned& r3, unsigned a) {
    asm volatile("ldmatrix.sync.aligned.m8n8.x4.shared.b16 {%0,%1,%2,%3}, [%4];"
                 : "=r"(r0), "=r"(r1), "=r"(r2), "=r"(r3) : "r"(a));
}
__device__ __forceinline__ void ldmx4t(unsigned& r0, unsigned& r1,
                                       unsigned& r2, unsigned& r3, unsigned a) {
    asm volatile("ldmatrix.sync.aligned.m8n8.x4.trans.shared.b16 {%0,%1,%2,%3}, [%4];"
                 : "=r"(r0), "=r"(r1), "=r"(r2), "=r"(r3) : "r"(a));
}
__device__ __forceinline__ void cp16(void* sdst, const void* gsrc) {
    asm volatile("cp.async.cg.shared.global [%0], [%1], 16;"
                 :: "r"(smem_u32(sdst)), "l"(gsrc));
}

// Prep: fp32 K/V -> fp16 device globals (one-shot, DRAM-bound, ~8us).
__global__ void __launch_bounds__(256) convert_kv(
    const float4* __restrict__ k4, const float4* __restrict__ v4)
{
    const size_t i = (size_t)blockIdx.x * 256 + threadIdx.x;
    float4 a = k4[i];
    float4 b = v4[i];
    uint2 ua, ub;
    ua.x = packh2(a.x, a.y); ua.y = packh2(a.z, a.w);
    ub.x = packh2(b.x, b.y); ub.y = packh2(b.z, b.w);
    ((uint2*)g_Kh)[i] = ua;
    ((uint2*)g_Vh)[i] = ub;
}

// Warp-specialized fused attention. Warps 0-7: QK producers (QK mma, exp,
// prob STG, P -> smem ring). Warps 8-15: PV consumers (P/V -> ctx), running
// one tile behind. One bar.sync per iteration; both roles' mma overlap.
__global__ void __launch_bounds__(THREADS, 1) attn_fused(
    const float* __restrict__ q, float* __restrict__ out)
{
    extern __shared__ __align__(16) char smraw[];
    half* Ks = (half*)smraw;                     // [2][64][136]
    half* Vs = (half*)(smraw + KS_BYTES);        // [2][64][136]
    half* Ps = (half*)(smraw + 2 * KS_BYTES);    // [2][8 warps][16][72]
    __shared__ float izbuf[TM];

#define KS_(bb,r,c)    Ks[((bb)*TN + (r))*136 + (c)]
#define VS_(bb,r,c)    Vs[((bb)*TN + (r))*136 + (c)]
#define PS_(ss,pp,r,c) Ps[(((ss)*8 + (pp))*16 + (r))*PS_STRIDE + (c)]

    float* ctx   = out;
    float* attn  = out + CTX_ELEMS;
    half*  attnh = (half*)(out + CTX_ELEMS);   // packed fp16 probs (low half of rows)

    const int b    = blockIdx.y;
    const int qt   = blockIdx.x;
    const int tid  = threadIdx.x;
    const int w    = tid >> 5;
    const int lane = tid & 31;
    const int g    = lane >> 2;
    const int i4   = lane & 3;
    const bool prod = (w < 8);
    const int pw   = prod ? w : (w - 8);   // role-local warp index: 16 q-rows each
    const int ltid = prod ? tid : (tid - 256);

    const int gr0 = b * S_ + qt * TM;
    const int lr0 = pw * 16 + g;
    const int lr1 = lr0 + 8;
    const int r0 = gr0 + lr0;
    const int r1 = gr0 + lr1;

    const half* gK = g_Kh + (size_t)b * S_ * D_;
    const half* gV = g_Vh + (size_t)b * S_ * D_;

    const int lm_row = (lane & 7);
    const int lm_m   = lane >> 3;

    if (prod) {
        // ==================== PRODUCER: QK + softmax-numerator =============
        // Q fragments in regs, scale*log2e folded
        const float SC = 0.08838834764831845f * 1.4426950408889634f;
        unsigned aq[8][4];
        {
            const float* q0 = q + (size_t)r0 * D_;
            const float* q1 = q + (size_t)r1 * D_;
            #pragma unroll
            for (int ks = 0; ks < 8; ks++) {
                const int c = ks * 16 + 2 * i4;
                float2 x0 = *(const float2*)(q0 + c);
                float2 x1 = *(const float2*)(q1 + c);
                float2 x2 = *(const float2*)(q0 + c + 8);
                float2 x3 = *(const float2*)(q1 + c + 8);
                aq[ks][0] = packh2(x0.x * SC, x0.y * SC);
                aq[ks][1] = packh2(x1.x * SC, x1.y * SC);
                aq[ks][2] = packh2(x2.x * SC, x2.y * SC);
                aq[ks][3] = packh2(x3.x * SC, x3.y * SC);
            }
        }

        // K tile loader: 256 producer threads, 4 x 16B chunks each
        auto issueK = [&](int kt, int bb) {
            const half* kg = gK + (size_t)kt * TN * D_;
            #pragma unroll
            for (int c = 0; c < 4; c++) {
                const int idx = c * 256 + ltid;
                const int row = idx >> 4;
                const int ch  = (idx & 15) * 8;
                cp16(&KS_(bb, row, ch), kg + row * D_ + ch);
            }
            asm volatile("cp.async.commit_group;");
        };
        issueK(0, 0);

        float zp0 = 0.f, zp1 = 0.f;

        for (int kt = 0; kt < KTILES; kt++) {
            const int bb = kt & 1;
            asm volatile("cp.async.wait_group 0;" ::: "memory");
            barsync();                              // bar_kt
            if (kt + 1 < KTILES) issueK(kt + 1, bb ^ 1);

            // QK: m16 x n64
            float sc[8][4];
            #pragma unroll
            for (int nt = 0; nt < 8; nt++)
                #pragma unroll
                for (int j = 0; j < 4; j++) sc[nt][j] = 0.f;

            #pragma unroll
            for (int ks = 0; ks < 8; ks++) {
                unsigned kb[8][2];
                #pragma unroll
                for (int p = 0; p < 4; p++) {
                    const int row = p * 16 + (lm_m >> 1) * 8 + lm_row;
                    const int col = ks * 16 + (lm_m & 1) * 8;
                    ldmx4(kb[2*p][0], kb[2*p][1], kb[2*p+1][0], kb[2*p+1][1],
                          smem_u32(&KS_(bb, row, col)));
                }
                #pragma unroll
                for (int nt = 0; nt < 8; nt++)
                    mma16816(sc[nt], aq[ks], kb[nt][0], kb[nt][1]);
            }

            // exp + rowsum + pack
            unsigned ph0[8], ph1[8];
            #pragma unroll
            for (int nt = 0; nt < 8; nt++) {
                float e0 = ex2f(sc[nt][0]), e1 = ex2f(sc[nt][1]);
                float e2 = ex2f(sc[nt][2]), e3 = ex2f(sc[nt][3]);
                zp0 += e0 + e1;
                zp1 += e2 + e3;
                ph0[nt] = packh2(e0, e1);
                ph1[nt] = packh2(e2, e3);
            }

            // packed probs -> gmem (unnormalized)
            {
                half* a0 = attnh + (size_t)r0 * 4096 + kt * TN + 2 * i4;
                half* a1 = attnh + (size_t)r1 * 4096 + kt * TN + 2 * i4;
                #pragma unroll
                for (int nt = 0; nt < 8; nt++) {
                    *(unsigned*)(a0 + nt * 8) = ph0[nt];
                    *(unsigned*)(a1 + nt * 8) = ph1[nt];
                }
            }

            // P -> smem ring slot kt&1 (consumed by PV warps next iter)
            #pragma unroll
            for (int nt = 0; nt < 8; nt++) {
                const int col = nt * 8 + 2 * i4;
                *(unsigned*)&PS_(bb, pw, g,     col) = ph0[nt];
                *(unsigned*)&PS_(bb, pw, g + 8, col) = ph1[nt];
            }
        }

        barsync();                                  // bar_KTILES
        // rowsum reduce (producer owns the full row) -> izbuf
        float z0 = zp0;
        z0 += __shfl_xor_sync(0xffffffffu, z0, 1);
        z0 += __shfl_xor_sync(0xffffffffu, z0, 2);
        float z1 = zp1;
        z1 += __shfl_xor_sync(0xffffffffu, z1, 1);
        z1 += __shfl_xor_sync(0xffffffffu, z1, 2);
        if (i4 == 0) {
            izbuf[lr0] = 1.0f / z0;
            izbuf[lr1] = 1.0f / z1;
        }
        barsync();                                  // bar_final
    } else {
        // ==================== CONSUMER: PV + context =======================
        auto issueV = [&](int kt, int bb) {
            const half* vg = gV + (size_t)kt * TN * D_;
            #pragma unroll
            for (int c = 0; c < 4; c++) {
                const int idx = c * 256 + ltid;
                const int row = idx >> 4;
                const int ch  = (idx & 15) * 8;
                cp16(&VS_(bb, row, ch), vg + row * D_ + ch);
            }
            asm volatile("cp.async.commit_group;");
        };

        float acc[16][4];
        #pragma unroll
        for (int nt = 0; nt < 16; nt++)
            #pragma unroll
            for (int j = 0; j < 4; j++) acc[nt][j] = 0.f;

        const unsigned paddr0 =
            smem_u32(&PS_(0, pw, (lane & 15), (lane >> 4) * 8));
        const unsigned pslot_bytes = 8 * 16 * PS_STRIDE * 2;  // ring slot stride

        for (int it = 0; it <= KTILES; it++) {
            asm volatile("cp.async.wait_group 0;" ::: "memory");
            barsync();                              // bar_it
            if (it < KTILES) issueV(it, it & 1);

            if (it > 0) {
                const int kt = it - 1;              // tile being consumed
                const int bb = kt & 1;
                const unsigned pbase = paddr0 + bb * pslot_bytes;
                #pragma unroll
                for (int kk = 0; kk < 4; kk++) {
                    unsigned pa[4];
                    ldmx4(pa[0], pa[1], pa[2], pa[3], pbase + kk * 32);
                    #pragma unroll
                    for (int ntp = 0; ntp < 8; ntp++) {
                        const int row = kk * 16 + (lane & 15);
                        const int col = (ntp * 2 + (lane >> 4)) * 8;
                        unsigned b0, b1, b2, b3;
                        ldmx4t(b0, b1, b2, b3, smem_u32(&VS_(bb, row, col)));
                        mma16816(acc[2*ntp],     pa, b0, b1);
                        mma16816(acc[2*ntp + 1], pa, b2, b3);
                    }
                }
            }
        }

        barsync();                                  // bar_final
        const float iz0 = izbuf[lr0];
        const float iz1 = izbuf[lr1];

        float* c0p = ctx + (size_t)r0 * D_ + 2 * i4;
        float* c1p = ctx + (size_t)r1 * D_ + 2 * i4;
        #pragma unroll
        for (int nt = 0; nt < 16; nt++) {
            *(float2*)(c0p + nt * 8) = make_float2(acc[nt][0] * iz0, acc[nt][1] * iz0);
            *(float2*)(c1p + nt * 8) = make_float2(acc[nt][2] * iz1, acc[nt][3] * iz1);
        }
    }

    // ================= tail: in-place expand this CTA's attn rows ==========
    // probs STG'd before bar_KTILES; izbuf before bar_final -> visible here.
    barsync();

    const int t = tid & 127;                // 128 threads per row
    #pragma unroll 1
    for (int c = 0; c < TM / 4; c++) {      // 4 rows per pass
        const int lr = c * 4 + (tid >> 7);
        const float iz = izbuf[lr];
        const uint4* src = (const uint4*)(attnh + (size_t)(gr0 + lr) * 4096);

        float4 outv[4];
        #pragma unroll
        for (int j = 0; j < 2; j++) {
            uint4 raw = src[t + j * 128];
            const __half2* hp = (const __half2*)&raw;
            float2 f0 = __half22float2(hp[0]);
            float2 f1 = __half22float2(hp[1]);
            float2 f2 = __half22float2(hp[2]);
            float2 f3 = __half22float2(hp[3]);
            outv[2*j]   = make_float4(f0.x * iz, f0.y * iz, f1.x * iz, f1.y * iz);
            outv[2*j+1] = make_float4(f2.x * iz, f2.y * iz, f3.x * iz, f3.y * iz);
        }
        barsync();          // all reads of these 4 rows complete before writes

        float4* dst = (float4*)(attn + (size_t)(gr0 + lr) * S_);
        #pragma unroll
        for (int j = 0; j < 2; j++) {
            dst[2 * (t + j * 128)]     = outv[2*j];
            dst[2 * (t + j * 128) + 1] = outv[2*j+1];
        }
    }
}

extern "C" void kernel_launch(void* const* d_in, const int* in_sizes, int n_in,
                              void* d_out, int out_size)
{
    const float* q = (const float*)d_in[0];
    const float* k = (const float*)d_in[1];
    const float* v = (const float*)d_in[2];
    float* out = (float*)d_out;

    static bool attr_set = false;
    if (!attr_set) {
        cudaFuncSetAttribute(attn_fused, cudaFuncAttributeMaxDynamicSharedMemorySize,
                             SMEM_MAIN);
        attr_set = true;
    }

    convert_kv<<<(B_ * S_ * D_) / 4 / 256, 256>>>((const float4*)k, (const float4*)v);
    dim3 g1(S_ / TM, B_);
    attn_fused<<<g1, THREADS, SMEM_MAIN>>>(q, out);
}